// round 1
// baseline (speedup 1.0000x reference)
#include <cuda_runtime.h>
#include <math.h>

#define MREL 8
#define DDIM 256
#define MAXN 51200

// Scratch (no cudaMalloc allowed): 4 x 52.4 MB
__device__ float g_zsum[(size_t)MAXN * DDIM];
__device__ float g_zmax[(size_t)MAXN * DDIM];
__device__ float g_zagr[(size_t)MAXN * DDIM];
__device__ float g_zpre[(size_t)MAXN * DDIM];

typedef unsigned long long u64;

__device__ __forceinline__ u64 pack2(float lo, float hi) {
    u64 r; asm("mov.b64 %0, {%1, %2};" : "=l"(r) : "f"(lo), "f"(hi)); return r;
}
__device__ __forceinline__ void unpack2(u64 v, float &lo, float &hi) {
    asm("mov.b64 {%0, %1}, %2;" : "=f"(lo), "=f"(hi) : "l"(v));
}
// Packed dual-FMA: d.lo += a.lo*b.lo ; d.hi += a.hi*b.hi  (sm_103a f32x2 path)
__device__ __forceinline__ void fma2(u64 &d, u64 a, u64 b) {
    asm("fma.rn.f32x2 %0, %1, %2, %0;" : "+l"(d) : "l"(a), "l"(b));
}

// ============================================================================
// Kernel 1: gate (softmax over relations) + z_sum.  One warp per node.
// cat[n, m*D+d] = zs[m,n,d];  logits[n,j] = sum cat*Wb[:,j] + bb[j]
// ============================================================================
__global__ void k_gate_zsum(const float* __restrict__ zs,
                            const float* __restrict__ Wb,
                            const float* __restrict__ bb,
                            int N) {
    extern __shared__ float swb[];  // 2048*8 floats = 64 KB
    int tid = threadIdx.x;
    for (int i = tid; i < (MREL * DDIM * MREL) / 4; i += blockDim.x)
        ((float4*)swb)[i] = ((const float4*)Wb)[i];
    __syncthreads();

    int lane = tid & 31;
    int wid  = tid >> 5;
    int warps_per_block = blockDim.x >> 5;
    int stride = warps_per_block * gridDim.x;

    float bbv[8];
#pragma unroll
    for (int j = 0; j < 8; j++) bbv[j] = bb[j];

    for (int n = blockIdx.x * warps_per_block + wid; n < N; n += stride) {
        float vals[MREL][8];
#pragma unroll
        for (int m = 0; m < MREL; m++) {
            const float* p = zs + ((size_t)m * N + n) * DDIM + lane * 8;
            float4 v0 = *(const float4*)p;
            float4 v1 = *(const float4*)(p + 4);
            vals[m][0] = v0.x; vals[m][1] = v0.y; vals[m][2] = v0.z; vals[m][3] = v0.w;
            vals[m][4] = v1.x; vals[m][5] = v1.y; vals[m][6] = v1.z; vals[m][7] = v1.w;
        }
        float lg[8] = {0.f,0.f,0.f,0.f,0.f,0.f,0.f,0.f};
#pragma unroll
        for (int m = 0; m < MREL; m++) {
#pragma unroll
            for (int dd = 0; dd < 8; dd++) {
                const float* w = swb + (size_t)(m * DDIM + lane * 8 + dd) * 8;
                float4 w0 = *(const float4*)w;
                float4 w1 = *(const float4*)(w + 4);
                float v = vals[m][dd];
                lg[0] = fmaf(v, w0.x, lg[0]); lg[1] = fmaf(v, w0.y, lg[1]);
                lg[2] = fmaf(v, w0.z, lg[2]); lg[3] = fmaf(v, w0.w, lg[3]);
                lg[4] = fmaf(v, w1.x, lg[4]); lg[5] = fmaf(v, w1.y, lg[5]);
                lg[6] = fmaf(v, w1.z, lg[6]); lg[7] = fmaf(v, w1.w, lg[7]);
            }
        }
#pragma unroll
        for (int off = 16; off > 0; off >>= 1) {
#pragma unroll
            for (int j = 0; j < 8; j++)
                lg[j] += __shfl_xor_sync(0xffffffffu, lg[j], off);
        }
        float mx = -1e30f;
#pragma unroll
        for (int j = 0; j < 8; j++) { lg[j] += bbv[j]; mx = fmaxf(mx, lg[j]); }
        float g[8], se = 0.f;
#pragma unroll
        for (int j = 0; j < 8; j++) { g[j] = expf(lg[j] - mx); se += g[j]; }
        float inv = 1.f / se;
        float o[8];
#pragma unroll
        for (int dd = 0; dd < 8; dd++) {
            float a = 0.f;
#pragma unroll
            for (int m = 0; m < MREL; m++) a = fmaf(g[m], vals[m][dd], a);
            o[dd] = a * inv;
        }
        float* q = g_zsum + (size_t)n * DDIM + lane * 8;
        *(float4*)q       = make_float4(o[0], o[1], o[2], o[3]);
        *(float4*)(q + 4) = make_float4(o[4], o[5], o[6], o[7]);
    }
}

// ============================================================================
// Kernel 2: the heavy part. For each relation m: proj = zs[m]@Wmax[m]+bmax[m],
// phi = zs[m]@Wphi[m]+bphi[m]; fold z_max = max_m proj, s1 = sum phi,
// s2 = sum phi^2; write z_max and z_agr = 0.5*(s1^2 - s2).
// Tiled 64(nodes) x 64(out) x 16(k), dual-GEMM sharing the A operand,
// inner loop in packed f32x2.
// ============================================================================
__global__ void __launch_bounds__(256, 2) k_maxphi(
        const float* __restrict__ zs,
        const float* __restrict__ Wmax, const float* __restrict__ bmax,
        const float* __restrict__ Wphi, const float* __restrict__ bphi,
        int N) {
    __shared__ float As[16][68];
    __shared__ float Bm[16][64];
    __shared__ float Bp[16][64];

    int tid = threadIdx.x;
    int tx = tid & 15, ty = tid >> 4;
    int n0 = blockIdx.x * 64;
    int e0 = blockIdx.y * 64;

    float cmax[4][4], cs1[4][4], cs2[4][4];
#pragma unroll
    for (int r = 0; r < 4; r++)
#pragma unroll
        for (int c = 0; c < 4; c++) { cmax[r][c] = -1e30f; cs1[r][c] = 0.f; cs2[r][c] = 0.f; }

    int ai = tid >> 2;
    int ak = (tid & 3) * 4;
    const bool aval = (n0 + ai) < N;

    for (int m = 0; m < MREL; m++) {
        u64 accP[4][2], accF[4][2];
#pragma unroll
        for (int r = 0; r < 4; r++) { accP[r][0] = accP[r][1] = 0ull; accF[r][0] = accF[r][1] = 0ull; }

        const float* za = zs + (size_t)m * N * DDIM + (size_t)(aval ? (n0 + ai) : 0) * DDIM + ak;
        const float* wm = Wmax + (size_t)m * DDIM * DDIM + (size_t)ty * DDIM + e0 + tx * 4;
        const float* wp = Wphi + (size_t)m * DDIM * DDIM + (size_t)ty * DDIM + e0 + tx * 4;

        for (int k0 = 0; k0 < DDIM; k0 += 16) {
            float4 av = make_float4(0.f, 0.f, 0.f, 0.f);
            if (aval) av = *(const float4*)(za + k0);
            As[ak + 0][ai] = av.x; As[ak + 1][ai] = av.y;
            As[ak + 2][ai] = av.z; As[ak + 3][ai] = av.w;
            *(float4*)&Bm[ty][tx * 4] = *(const float4*)(wm + (size_t)k0 * DDIM);
            *(float4*)&Bp[ty][tx * 4] = *(const float4*)(wp + (size_t)k0 * DDIM);
            __syncthreads();
#pragma unroll
            for (int kk = 0; kk < 16; kk++) {
                float4 a = *(const float4*)&As[kk][ty * 4];
                u64 ap0 = pack2(a.x, a.x), ap1 = pack2(a.y, a.y);
                u64 ap2 = pack2(a.z, a.z), ap3 = pack2(a.w, a.w);
                ulonglong2 bm2 = *(const ulonglong2*)&Bm[kk][tx * 4];
                ulonglong2 bp2 = *(const ulonglong2*)&Bp[kk][tx * 4];
                fma2(accP[0][0], ap0, bm2.x); fma2(accP[0][1], ap0, bm2.y);
                fma2(accP[1][0], ap1, bm2.x); fma2(accP[1][1], ap1, bm2.y);
                fma2(accP[2][0], ap2, bm2.x); fma2(accP[2][1], ap2, bm2.y);
                fma2(accP[3][0], ap3, bm2.x); fma2(accP[3][1], ap3, bm2.y);
                fma2(accF[0][0], ap0, bp2.x); fma2(accF[0][1], ap0, bp2.y);
                fma2(accF[1][0], ap1, bp2.x); fma2(accF[1][1], ap1, bp2.y);
                fma2(accF[2][0], ap2, bp2.x); fma2(accF[2][1], ap2, bp2.y);
                fma2(accF[3][0], ap3, bp2.x); fma2(accF[3][1], ap3, bp2.y);
            }
            __syncthreads();
        }
        float bmv[4], bpv[4];
#pragma unroll
        for (int c = 0; c < 4; c++) {
            bmv[c] = __ldg(bmax + m * DDIM + e0 + tx * 4 + c);
            bpv[c] = __ldg(bphi + m * DDIM + e0 + tx * 4 + c);
        }
#pragma unroll
        for (int r = 0; r < 4; r++) {
            float p[4], f[4];
            unpack2(accP[r][0], p[0], p[1]); unpack2(accP[r][1], p[2], p[3]);
            unpack2(accF[r][0], f[0], f[1]); unpack2(accF[r][1], f[2], f[3]);
#pragma unroll
            for (int c = 0; c < 4; c++) {
                float pv = p[c] + bmv[c];
                cmax[r][c] = fmaxf(cmax[r][c], pv);
                float fv = f[c] + bpv[c];
                cs1[r][c] += fv;
                cs2[r][c] = fmaf(fv, fv, cs2[r][c]);
            }
        }
    }
#pragma unroll
    for (int r = 0; r < 4; r++) {
        int n = n0 + ty * 4 + r;
        if (n < N) {
            size_t off = (size_t)n * DDIM + e0 + tx * 4;
            *(float4*)(g_zmax + off) =
                make_float4(cmax[r][0], cmax[r][1], cmax[r][2], cmax[r][3]);
            float a0 = 0.5f * (cs1[r][0] * cs1[r][0] - cs2[r][0]);
            float a1 = 0.5f * (cs1[r][1] * cs1[r][1] - cs2[r][1]);
            float a2 = 0.5f * (cs1[r][2] * cs1[r][2] - cs2[r][2]);
            float a3 = 0.5f * (cs1[r][3] * cs1[r][3] - cs2[r][3]);
            *(float4*)(g_zagr + off) = make_float4(a0, a1, a2, a3);
        }
    }
}

// ============================================================================
// Kernel 3: z_pre = concat(z_sum, z_max, z_agr) @ Wc + bc.  K = 768.
// ============================================================================
__global__ void __launch_bounds__(256, 2) k_combine(
        const float* __restrict__ Wc, const float* __restrict__ bc, int N) {
    __shared__ float As[16][68];
    __shared__ float Bs[16][64];

    int tid = threadIdx.x;
    int tx = tid & 15, ty = tid >> 4;
    int n0 = blockIdx.x * 64;
    int e0 = blockIdx.y * 64;

    u64 acc[4][2];
#pragma unroll
    for (int r = 0; r < 4; r++) { acc[r][0] = 0ull; acc[r][1] = 0ull; }

    int ai = tid >> 2;
    int ak = (tid & 3) * 4;
    const bool aval = (n0 + ai) < N;
    size_t arow = (size_t)(aval ? (n0 + ai) : 0) * DDIM + ak;

    for (int k0 = 0; k0 < 3 * DDIM; k0 += 16) {
        const float* src = (k0 < DDIM) ? g_zsum : (k0 < 2 * DDIM) ? g_zmax : g_zagr;
        int kc = k0 & (DDIM - 1);
        float4 av = make_float4(0.f, 0.f, 0.f, 0.f);
        if (aval) av = *(const float4*)(src + arow + kc);
        As[ak + 0][ai] = av.x; As[ak + 1][ai] = av.y;
        As[ak + 2][ai] = av.z; As[ak + 3][ai] = av.w;
        *(float4*)&Bs[ty][tx * 4] = *(const float4*)(Wc + (size_t)(k0 + ty) * DDIM + e0 + tx * 4);
        __syncthreads();
#pragma unroll
        for (int kk = 0; kk < 16; kk++) {
            float4 a = *(const float4*)&As[kk][ty * 4];
            u64 ap0 = pack2(a.x, a.x), ap1 = pack2(a.y, a.y);
            u64 ap2 = pack2(a.z, a.z), ap3 = pack2(a.w, a.w);
            ulonglong2 b2 = *(const ulonglong2*)&Bs[kk][tx * 4];
            fma2(acc[0][0], ap0, b2.x); fma2(acc[0][1], ap0, b2.y);
            fma2(acc[1][0], ap1, b2.x); fma2(acc[1][1], ap1, b2.y);
            fma2(acc[2][0], ap2, b2.x); fma2(acc[2][1], ap2, b2.y);
            fma2(acc[3][0], ap3, b2.x); fma2(acc[3][1], ap3, b2.y);
        }
        __syncthreads();
    }
    float bcv[4];
#pragma unroll
    for (int c = 0; c < 4; c++) bcv[c] = __ldg(bc + e0 + tx * 4 + c);
#pragma unroll
    for (int r = 0; r < 4; r++) {
        int n = n0 + ty * 4 + r;
        if (n < N) {
            float v[4];
            unpack2(acc[r][0], v[0], v[1]); unpack2(acc[r][1], v[2], v[3]);
            size_t off = (size_t)n * DDIM + e0 + tx * 4;
            *(float4*)(g_zpre + off) =
                make_float4(v[0] + bcv[0], v[1] + bcv[1], v[2] + bcv[2], v[3] + bcv[3]);
        }
    }
}

// ============================================================================
// Kernel 4: LayerNorm.  One warp per node.
// ============================================================================
__global__ void k_ln(const float* __restrict__ gamma, const float* __restrict__ beta,
                     float* __restrict__ out, int N) {
    int tid = threadIdx.x;
    int lane = tid & 31;
    int wid = tid >> 5;
    int n = blockIdx.x * (blockDim.x >> 5) + wid;
    if (n >= N) return;

    const float* p = g_zpre + (size_t)n * DDIM + lane * 8;
    float4 v0 = *(const float4*)p;
    float4 v1 = *(const float4*)(p + 4);
    float v[8] = {v0.x, v0.y, v0.z, v0.w, v1.x, v1.y, v1.z, v1.w};
    float s = 0.f, q = 0.f;
#pragma unroll
    for (int dd = 0; dd < 8; dd++) { s += v[dd]; q = fmaf(v[dd], v[dd], q); }
#pragma unroll
    for (int off = 16; off > 0; off >>= 1) {
        s += __shfl_xor_sync(0xffffffffu, s, off);
        q += __shfl_xor_sync(0xffffffffu, q, off);
    }
    float mean = s * (1.f / 256.f);
    float var = q * (1.f / 256.f) - mean * mean;
    float inv = rsqrtf(var + 1e-5f);

    const float* gp = gamma + lane * 8;
    const float* bp = beta + lane * 8;
    float4 g0 = *(const float4*)gp, g1 = *(const float4*)(gp + 4);
    float4 b0 = *(const float4*)bp, b1 = *(const float4*)(bp + 4);
    float g[8] = {g0.x, g0.y, g0.z, g0.w, g1.x, g1.y, g1.z, g1.w};
    float b[8] = {b0.x, b0.y, b0.z, b0.w, b1.x, b1.y, b1.z, b1.w};
    float o[8];
#pragma unroll
    for (int dd = 0; dd < 8; dd++) o[dd] = fmaf((v[dd] - mean) * inv, g[dd], b[dd]);

    float* qo = out + (size_t)n * DDIM + lane * 8;
    *(float4*)qo       = make_float4(o[0], o[1], o[2], o[3]);
    *(float4*)(qo + 4) = make_float4(o[4], o[5], o[6], o[7]);
}

// ============================================================================
extern "C" void kernel_launch(void* const* d_in, const int* in_sizes, int n_in,
                              void* d_out, int out_size) {
    const float* zs    = (const float*)d_in[0];
    const float* Wb    = (const float*)d_in[1];
    const float* bb    = (const float*)d_in[2];
    const float* Wmax  = (const float*)d_in[3];
    const float* bmax  = (const float*)d_in[4];
    const float* Wphi  = (const float*)d_in[5];
    const float* bphi  = (const float*)d_in[6];
    const float* Wc    = (const float*)d_in[7];
    const float* bc    = (const float*)d_in[8];
    const float* gamma = (const float*)d_in[9];
    const float* beta  = (const float*)d_in[10];
    float* out = (float*)d_out;

    int N = in_sizes[0] / (MREL * DDIM);

    cudaFuncSetAttribute(k_gate_zsum, cudaFuncAttributeMaxDynamicSharedMemorySize, 65536);
    k_gate_zsum<<<592, 256, 65536>>>(zs, Wb, bb, N);

    dim3 g2((N + 63) / 64, DDIM / 64);
    k_maxphi<<<g2, 256>>>(zs, Wmax, bmax, Wphi, bphi, N);
    k_combine<<<g2, 256>>>(Wc, bc, N);

    k_ln<<<(N + 7) / 8, 256>>>(gamma, beta, out, N);
}